// round 11
// baseline (speedup 1.0000x reference)
#include <cuda_runtime.h>
#include <cuda_bf16.h>
#include <math.h>
#include <stdint.h>

// Problem constants
#define Bn 65536
#define Cc 2
#define Vv 3
#define Dd 64
#define Kk 1024
#define Ss 4
#define Hh 1024
#define Ll 5
#define Ff 25
#define INDIM 102      // C*(2F+1)
#define INPAD2 128     // layer-0 K padded to 128

// GEMM tiling (mma.sync path, base sm_103 compatible)
#define BM 128
#define BN 128
#define BK 32
#define STAGES 3
#define STG_BYTES 32768              // A tile 16KB (hi+lo interleaved) + B tile 16KB
#define SMEM_DYN (STAGES * STG_BYTES)

// ---------------------------------------------------------------------------
// Device-global scratch (no allocations allowed)
// ---------------------------------------------------------------------------
__device__ __align__(16) __nv_bfloat16 g_pe_hi[(size_t)Bn * INPAD2];
__device__ __align__(16) __nv_bfloat16 g_pe_lo[(size_t)Bn * INPAD2];
__device__ __align__(16) __nv_bfloat16 g_h0_hi[(size_t)Bn * Hh];
__device__ __align__(16) __nv_bfloat16 g_h0_lo[(size_t)Bn * Hh];
__device__ __align__(16) __nv_bfloat16 g_h1_hi[(size_t)Bn * Hh];
__device__ __align__(16) __nv_bfloat16 g_h1_lo[(size_t)Bn * Hh];
__device__ __align__(16) __nv_bfloat16 g_w0t_hi[(size_t)Hh * INPAD2];  // [n][k]
__device__ __align__(16) __nv_bfloat16 g_w0t_lo[(size_t)Hh * INPAD2];
__device__ __align__(16) __nv_bfloat16 g_wht_hi[4 * (size_t)Hh * Hh]; // [l][n][k]
__device__ __align__(16) __nv_bfloat16 g_wht_lo[4 * (size_t)Hh * Hh];
__device__ __align__(16) float g_bias[Ll * Hh];

// ---------------------------------------------------------------------------
// PTX helpers (all base-arch: cp.async sm_80, ldmatrix sm_75, mma bf16 sm_80)
// ---------------------------------------------------------------------------
__device__ __forceinline__ uint32_t smem_u32(const void* p) {
    uint32_t a;
    asm("{ .reg .u64 t; cvta.to.shared.u64 t, %1; cvt.u32.u64 %0, t; }"
        : "=r"(a) : "l"(p));
    return a;
}
__device__ __forceinline__ void cp16(uint32_t s, const void* g) {
    asm volatile("cp.async.cg.shared.global [%0], [%1], 16;" :: "r"(s), "l"(g));
}
#define CP_COMMIT() asm volatile("cp.async.commit_group;" ::: "memory")
#define CP_WAIT1()  asm volatile("cp.async.wait_group 1;" ::: "memory")

__device__ __forceinline__ void ldsm4(uint32_t* r, uint32_t addr) {
    asm volatile("ldmatrix.sync.aligned.m8n8.x4.shared.b16 {%0,%1,%2,%3}, [%4];"
        : "=r"(r[0]), "=r"(r[1]), "=r"(r[2]), "=r"(r[3]) : "r"(addr));
}
__device__ __forceinline__ void mma16816(float* d, const uint32_t* a,
                                         uint32_t b0, uint32_t b1) {
    asm volatile(
        "mma.sync.aligned.m16n8k16.row.col.f32.bf16.bf16.f32 "
        "{%0,%1,%2,%3}, {%4,%5,%6,%7}, {%8,%9}, {%0,%1,%2,%3};"
        : "+f"(d[0]), "+f"(d[1]), "+f"(d[2]), "+f"(d[3])
        : "r"(a[0]), "r"(a[1]), "r"(a[2]), "r"(a[3]), "r"(b0), "r"(b1));
}

// 128B-row SW128 swizzle: tile row (0..127), 16B unit u (0..7)
__device__ __forceinline__ uint32_t sw_addr(uint32_t base, int row, int u) {
    return base + (uint32_t)(row * 128) + (uint32_t)((u ^ (row & 7)) << 4);
}

// ---------------------------------------------------------------------------
// Setup: VQ (idx, loss, z_q_sum) + fold betas into per-layer biases.
// ---------------------------------------------------------------------------
__global__ void setup_kernel(const int* __restrict__ latent_idx,
                             const float* __restrict__ latents,
                             const float* __restrict__ codebooks,
                             const float* __restrict__ mod_W,
                             const float* __restrict__ mod_b,
                             const float* __restrict__ dec_b0,
                             const float* __restrict__ dec_bh,
                             float* __restrict__ out, int out_size)
{
    __shared__ float s_zqsum[Dd];
    __shared__ float s_res[Dd];
    __shared__ float s_zcur[Dd];
    __shared__ float s_dist[Kk];
    __shared__ int   s_idx[Kk];
    __shared__ float s_loss;
    __shared__ int   s_best[Ss];

    int tid = threadIdx.x;
    const float* img = latents + (size_t)(*latent_idx) * (Ss * Dd);

    if (tid < Dd) { s_zqsum[tid] = 0.f; s_res[tid] = 0.f; }
    if (tid == 0) s_loss = 0.f;
    __syncthreads();

    for (int s = 0; s < Ss; ++s) {
        if (tid < Dd) {
            float zs = img[s * Dd + tid];
            float rt = s_res[tid] + zs;
            s_res[tid] = rt;
            s_zcur[tid] = (s == 0) ? zs : (rt - s_zqsum[tid]);
        }
        __syncthreads();
        {
            const float* e = codebooks + ((size_t)s * Kk + tid) * Dd;
            float zz = 0.f, ee = 0.f, ze = 0.f;
            for (int d = 0; d < Dd; ++d) {
                float z = s_zcur[d], ev = e[d];
                zz += z * z; ee += ev * ev; ze += z * ev;
            }
            s_dist[tid] = zz - 2.f * ze + ee;
            s_idx[tid] = tid;
        }
        __syncthreads();
        for (int stride = Kk / 2; stride > 0; stride >>= 1) {
            if (tid < stride) {
                float d2 = s_dist[tid + stride];
                float d1 = s_dist[tid];
                int   i2 = s_idx[tid + stride];
                if (d2 < d1 || (d2 == d1 && i2 < s_idx[tid])) {
                    s_dist[tid] = d2; s_idx[tid] = i2;
                }
            }
            __syncthreads();
        }
        int best = s_idx[0];
        if (tid == 0) {
            const float* e = codebooks + ((size_t)s * Kk + best) * Dd;
            float acc = 0.f;
            for (int d = 0; d < Dd; ++d) { float df = e[d] - s_zcur[d]; acc += df * df; }
            s_loss += 0.25f * (acc / (float)Dd);
            s_best[s] = best;
        }
        if (tid < Dd) {
            const float* e = codebooks + ((size_t)s * Kk + best) * Dd;
            float zq = e[tid];
            float zqst = zq + (s_zcur[tid] - zq);
            s_zqsum[tid] += zqst;
        }
        __syncthreads();
    }

    for (int l = 0; l < Ll; ++l) {
        float acc = mod_b[l * Hh + tid];
        const float* w = mod_W + (size_t)l * Dd * Hh + tid;
        #pragma unroll 4
        for (int d = 0; d < Dd; ++d) acc += s_zqsum[d] * w[(size_t)d * Hh];
        acc += (l == 0) ? dec_b0[tid] : dec_bh[(l - 1) * Hh + tid];
        g_bias[l * Hh + tid] = acc;
    }

    const int base = Bn * Vv;
    if (out_size >= base + Ss + 1) {
        if (tid < Ss) out[base + tid] = (float)s_best[tid];
        if (tid == 0) out[base + Ss] = s_loss;
    }
}

// ---------------------------------------------------------------------------
// Positional encoding -> hi/lo bf16, padded to 128 cols.
// ---------------------------------------------------------------------------
__global__ void pe_kernel(const float* __restrict__ coords)
{
    int idx = blockIdx.x * blockDim.x + threadIdx.x;
    if (idx >= Bn * INPAD2) return;
    int b = idx >> 7, j = idx & 127;
    float v = 0.f;
    if (j < Cc) {
        v = coords[b * Cc + j];
    } else if (j < INDIM) {
        int r = j - Cc;
        int f = r >> 2, t = r & 3;
        int which = t >> 1, c = t & 1;
        float pf = exp2f((float)f) * 3.14159274101257324f;
        float ang = coords[b * Cc + c] * pf;
        double a = (double)ang;
        v = (float)((which == 0) ? sin(a) : cos(a));
    }
    __nv_bfloat16 h = __float2bfloat16_rn(v);
    g_pe_hi[idx] = h;
    g_pe_lo[idx] = __float2bfloat16_rn(v - __bfloat162float(h));
}

// Transpose+split dec_W0 [K=102(->128), N=1024] -> g_w0t [n][k]
__global__ void w0t_kernel(const float* __restrict__ W0)
{
    int idx = blockIdx.x * blockDim.x + threadIdx.x;
    if (idx >= Hh * INPAD2) return;
    int n = idx >> 7, k = idx & 127;
    float v = (k < INDIM) ? W0[(size_t)k * Hh + n] : 0.f;
    __nv_bfloat16 h = __float2bfloat16_rn(v);
    g_w0t_hi[idx] = h;
    g_w0t_lo[idx] = __float2bfloat16_rn(v - __bfloat162float(h));
}

// Transpose+split dec_Wh [4][K=1024][N=1024] -> g_wht [l][n][k]
__global__ void wht_kernel(const float* __restrict__ Wh)
{
    size_t idx = (size_t)blockIdx.x * blockDim.x + threadIdx.x;
    if (idx >= 4 * (size_t)Hh * Hh) return;
    size_t l = idx >> 20;
    int n = (int)((idx >> 10) & 1023);
    int k = (int)(idx & 1023);
    float v = Wh[l * Hh * Hh + (size_t)k * Hh + n];
    __nv_bfloat16 h = __float2bfloat16_rn(v);
    g_wht_hi[idx] = h;
    g_wht_lo[idx] = __float2bfloat16_rn(v - __bfloat162float(h));
}

// ---------------------------------------------------------------------------
// Split-bf16 GEMM via mma.sync: C = relu(A@W + bias), A/W as hi+lo bf16 pairs.
// D += Ah*Bh + Ah*Bl + Al*Bh  (fp32 accumulate in registers)
// Tile: CTA 128x128, BK=32, 4 warps (warp tile 64x64), 3-stage cp.async.
// 64x64 warp tile: 48 FLOP per smem byte -> LDSM no longer co-limits HMMA.
// SMEM row: 128B = [hi k0..31 | lo k0..31], SW128 swizzled.
// B stored [n][k] K-major -> B fragments via PLAIN ldmatrix (non-trans).
// ---------------------------------------------------------------------------
__global__ __launch_bounds__(128, 2)
void gemm_mma_kernel(int a_sel, int w_sel, int bias_l, int out_sel, int K)
{
    extern __shared__ char dsm[];

    const __nv_bfloat16 *Ahi, *Alo, *Bhi, *Blo;
    if (a_sel == 0)      { Ahi = g_pe_hi; Alo = g_pe_lo; }
    else if (a_sel == 1) { Ahi = g_h0_hi; Alo = g_h0_lo; }
    else                 { Ahi = g_h1_hi; Alo = g_h1_lo; }
    if (w_sel < 0) { Bhi = g_w0t_hi; Blo = g_w0t_lo; }
    else {
        Bhi = g_wht_hi + (size_t)w_sel * Hh * Hh;
        Blo = g_wht_lo + (size_t)w_sel * Hh * Hh;
    }
    __nv_bfloat16* Ohi = (out_sel == 0) ? g_h0_hi : g_h1_hi;
    __nv_bfloat16* Olo = (out_sel == 0) ? g_h0_lo : g_h1_lo;

    const int tid  = threadIdx.x;
    const int wid  = tid >> 5;
    const int lane = tid & 31;
    const int wm = wid >> 1;          // 0..1 (M: rows wm*64..+63)
    const int wn = wid & 1;           // 0..1 (N: cols wn*64..+63)
    const int n0 = blockIdx.x * BN;
    const size_t m0 = (size_t)blockIdx.y * BM;

    const uint32_t sbase = smem_u32(dsm);

    float acc[4][8][4];
    #pragma unroll
    for (int i = 0; i < 4; ++i)
        #pragma unroll
        for (int j = 0; j < 8; ++j)
            #pragma unroll
            for (int q = 0; q < 4; ++q) acc[i][j][q] = 0.f;

    const int nkt = K / BK;

    // ---- tile loader: 1024 A units + 1024 B units, 16 cp16 per thread ----
    #define LOAD_STAGE(stg, kc) do {                                          \
        uint32_t sA = sbase + (stg) * STG_BYTES;                               \
        uint32_t sB = sA + 16384;                                              \
        _Pragma("unroll")                                                      \
        for (int j = 0; j < 8; ++j) {                                          \
            int i = tid + j * 128;                                             \
            int row = i >> 3, u = i & 7;                                       \
            uint32_t dst = sw_addr(0, row, u);                                 \
            const __nv_bfloat16* sa = (u < 4)                                  \
                ? (Ahi + (m0 + row) * K + (kc) + u * 8)                        \
                : (Alo + (m0 + row) * K + (kc) + (u - 4) * 8);                 \
            cp16(sA + dst, sa);                                                \
            const __nv_bfloat16* sbp = (u < 4)                                 \
                ? (Bhi + (size_t)(n0 + row) * K + (kc) + u * 8)                \
                : (Blo + (size_t)(n0 + row) * K + (kc) + (u - 4) * 8);         \
            cp16(sB + dst, sbp);                                               \
        }                                                                      \
    } while (0)

    // prologue: stages 0 and 1
    LOAD_STAGE(0, 0);
    CP_COMMIT();
    if (nkt > 1) LOAD_STAGE(1, BK);
    CP_COMMIT();

    const int lr = lane & 15;
    const int lh = lane >> 4;

    for (int c = 0; c < nkt; ++c) {
        CP_WAIT1();
        __syncthreads();

        // prefetch c+2 (stage reuse is safe: all warps passed the sync above,
        // so compute on iter c-1 — which used this stage — is complete)
        if (c + 2 < nkt) { int ns = (c + 2) % STAGES; LOAD_STAGE(ns, (c + 2) * BK); }
        CP_COMMIT();

        // compute on stage c%STAGES
        uint32_t sA = sbase + (c % STAGES) * STG_BYTES;
        uint32_t sB = sA + 16384;

        #pragma unroll
        for (int ks = 0; ks < 2; ++ks) {
            uint32_t af[4][4], bh[4][4], bt[4][4];
            // A hi fragments (units ks*2 + lh)
            #pragma unroll
            for (int mt = 0; mt < 4; ++mt)
                ldsm4(af[mt], sw_addr(sA, wm * 64 + mt * 16 + lr, ks * 2 + lh));
            // B hi fragments (non-trans: [n][k] rows give col-major B fragment)
            #pragma unroll
            for (int g = 0; g < 4; ++g)
                ldsm4(bh[g], sw_addr(sB, wn * 64 + g * 16 + lr, ks * 2 + lh));
            // Ah * Bh
            #pragma unroll
            for (int mt = 0; mt < 4; ++mt)
                #pragma unroll
                for (int nt = 0; nt < 8; ++nt)
                    mma16816(acc[mt][nt], af[mt],
                             bh[nt >> 1][nt & 1], bh[nt >> 1][2 + (nt & 1)]);
            // B lo fragments
            #pragma unroll
            for (int g = 0; g < 4; ++g)
                ldsm4(bt[g], sw_addr(sB, wn * 64 + g * 16 + lr, 4 + ks * 2 + lh));
            // Ah * Bl
            #pragma unroll
            for (int mt = 0; mt < 4; ++mt)
                #pragma unroll
                for (int nt = 0; nt < 8; ++nt)
                    mma16816(acc[mt][nt], af[mt],
                             bt[nt >> 1][nt & 1], bt[nt >> 1][2 + (nt & 1)]);
            // A lo fragments (reuse af)
            #pragma unroll
            for (int mt = 0; mt < 4; ++mt)
                ldsm4(af[mt], sw_addr(sA, wm * 64 + mt * 16 + lr, 4 + ks * 2 + lh));
            // Al * Bh
            #pragma unroll
            for (int mt = 0; mt < 4; ++mt)
                #pragma unroll
                for (int nt = 0; nt < 8; ++nt)
                    mma16816(acc[mt][nt], af[mt],
                             bh[nt >> 1][nt & 1], bh[nt >> 1][2 + (nt & 1)]);
        }
    }
    #undef LOAD_STAGE
    __syncthreads();

    // ---- epilogue: bias + relu + hi/lo split stores ----
    const float* bias = g_bias + bias_l * Hh + n0 + wn * 64;
    const int qr = lane >> 2;          // 0..7
    const int qc = (lane & 3) * 2;     // 0,2,4,6

    #pragma unroll
    for (int mt = 0; mt < 4; ++mt) {
        size_t r0 = m0 + wm * 64 + mt * 16 + qr;
        size_t r1 = r0 + 8;
        #pragma unroll
        for (int nt = 0; nt < 8; ++nt) {
            int cl = nt * 8 + qc;
            int col = n0 + wn * 64 + cl;
            float b0 = bias[cl], b1 = bias[cl + 1];
            float v00 = fmaxf(acc[mt][nt][0] + b0, 0.f);
            float v01 = fmaxf(acc[mt][nt][1] + b1, 0.f);
            float v10 = fmaxf(acc[mt][nt][2] + b0, 0.f);
            float v11 = fmaxf(acc[mt][nt][3] + b1, 0.f);
            __nv_bfloat16 h00 = __float2bfloat16_rn(v00);
            __nv_bfloat16 h01 = __float2bfloat16_rn(v01);
            __nv_bfloat16 h10 = __float2bfloat16_rn(v10);
            __nv_bfloat16 h11 = __float2bfloat16_rn(v11);
            *(__nv_bfloat162*)(Ohi + r0 * Hh + col) = __halves2bfloat162(h00, h01);
            *(__nv_bfloat162*)(Ohi + r1 * Hh + col) = __halves2bfloat162(h10, h11);
            *(__nv_bfloat162*)(Olo + r0 * Hh + col) = __halves2bfloat162(
                __float2bfloat16_rn(v00 - __bfloat162float(h00)),
                __float2bfloat16_rn(v01 - __bfloat162float(h01)));
            *(__nv_bfloat162*)(Olo + r1 * Hh + col) = __halves2bfloat162(
                __float2bfloat16_rn(v10 - __bfloat162float(h10)),
                __float2bfloat16_rn(v11 - __bfloat162float(h11)));
        }
    }
}

// ---------------------------------------------------------------------------
// Output projection: values[B,3] = (h_hi+h_lo) @ Wout + bout. One warp/row.
// ---------------------------------------------------------------------------
__global__ void out_kernel(const float* __restrict__ Wout,
                           const float* __restrict__ bout,
                           float* __restrict__ out)
{
    int gwarp = (blockIdx.x * blockDim.x + threadIdx.x) >> 5;
    int lane = threadIdx.x & 31;
    if (gwarp >= Bn) return;
    const __nv_bfloat16* hh = g_h0_hi + (size_t)gwarp * Hh;
    const __nv_bfloat16* hl = g_h0_lo + (size_t)gwarp * Hh;
    float a0 = 0.f, a1 = 0.f, a2 = 0.f;
    #pragma unroll 4
    for (int i = 0; i < 16; ++i) {
        int k = i * 64 + lane * 2;
        __nv_bfloat162 vh = *(const __nv_bfloat162*)(hh + k);
        __nv_bfloat162 vl = *(const __nv_bfloat162*)(hl + k);
        float h0 = __bfloat162float(vh.x) + __bfloat162float(vl.x);
        float h1 = __bfloat162float(vh.y) + __bfloat162float(vl.y);
        a0 += h0 * Wout[k * 3 + 0] + h1 * Wout[(k + 1) * 3 + 0];
        a1 += h0 * Wout[k * 3 + 1] + h1 * Wout[(k + 1) * 3 + 1];
        a2 += h0 * Wout[k * 3 + 2] + h1 * Wout[(k + 1) * 3 + 2];
    }
    #pragma unroll
    for (int off = 16; off; off >>= 1) {
        a0 += __shfl_down_sync(0xffffffffu, a0, off);
        a1 += __shfl_down_sync(0xffffffffu, a1, off);
        a2 += __shfl_down_sync(0xffffffffu, a2, off);
    }
    if (lane == 0) {
        out[gwarp * 3 + 0] = a0 + bout[0];
        out[gwarp * 3 + 1] = a1 + bout[1];
        out[gwarp * 3 + 2] = a2 + bout[2];
    }
}

// ---------------------------------------------------------------------------
extern "C" void kernel_launch(void* const* d_in, const int* in_sizes, int n_in,
                              void* d_out, int out_size)
{
    const float* coords     = (const float*)d_in[0];
    const int*   latent_idx = (const int*)  d_in[1];
    const float* latents    = (const float*)d_in[2];
    const float* codebooks  = (const float*)d_in[3];
    const float* mod_W      = (const float*)d_in[4];
    const float* mod_b      = (const float*)d_in[5];
    const float* dec_W0     = (const float*)d_in[6];
    const float* dec_b0     = (const float*)d_in[7];
    const float* dec_Wh     = (const float*)d_in[8];
    const float* dec_bh     = (const float*)d_in[9];
    const float* dec_Wout   = (const float*)d_in[10];
    const float* dec_bout   = (const float*)d_in[11];
    float* out = (float*)d_out;

    cudaFuncSetAttribute(gemm_mma_kernel,
                         cudaFuncAttributeMaxDynamicSharedMemorySize, SMEM_DYN);

    setup_kernel<<<1, 1024>>>(latent_idx, latents, codebooks, mod_W, mod_b,
                              dec_b0, dec_bh, out, out_size);
    pe_kernel<<<(Bn * INPAD2 + 255) / 256, 256>>>(coords);
    w0t_kernel<<<(Hh * INPAD2 + 255) / 256, 256>>>(dec_W0);
    wht_kernel<<<(int)((4 * (size_t)Hh * Hh + 255) / 256), 256>>>(dec_Wh);

    dim3 grid(Hh / BN, Bn / BM);   // (8, 512)
    // L0: pe @ W0t -> h0
    gemm_mma_kernel<<<grid, 128, SMEM_DYN>>>(0, -1, 0, 0, INPAD2);
    // hidden layers ping-pong h0 <-> h1
    gemm_mma_kernel<<<grid, 128, SMEM_DYN>>>(1, 0, 1, 1, Hh);
    gemm_mma_kernel<<<grid, 128, SMEM_DYN>>>(2, 1, 2, 0, Hh);
    gemm_mma_kernel<<<grid, 128, SMEM_DYN>>>(1, 2, 3, 1, Hh);
    gemm_mma_kernel<<<grid, 128, SMEM_DYN>>>(2, 3, 4, 0, Hh);
    // output projection reads h0
    out_kernel<<<(Bn * 32 + 255) / 256, 256>>>(dec_Wout, dec_bout, out);
}

// round 14
// speedup vs baseline: 1.5046x; 1.5046x over previous
#include <cuda_runtime.h>
#include <cuda_fp16.h>
#include <math.h>
#include <stdint.h>

// Problem constants
#define Bn 65536
#define Cc 2
#define Vv 3
#define Dd 64
#define Kk 1024
#define Ss 4
#define Hh 1024
#define Ll 5
#define Ff 25
#define INDIM 102      // C*(2F+1)
#define INPAD2 128     // layer-0 K padded to 128

// GEMM tiling (mma.sync path, base sm_103 compatible)
#define BM 128
#define BN 128
#define BK 64
#define STAGES 2
#define STG_BYTES 49152          // Ah 16KB + Al 16KB + B 16KB
#define OFF_AH 0
#define OFF_AL 16384
#define OFF_B  32768
#define SMEM_DYN (STAGES * STG_BYTES)

// ---------------------------------------------------------------------------
// Device-global scratch (no allocations allowed)
// ---------------------------------------------------------------------------
__device__ __align__(16) __half g_pe_hi[(size_t)Bn * INPAD2];
__device__ __align__(16) __half g_pe_lo[(size_t)Bn * INPAD2];
__device__ __align__(16) __half g_h0_hi[(size_t)Bn * Hh];
__device__ __align__(16) __half g_h0_lo[(size_t)Bn * Hh];
__device__ __align__(16) __half g_h1_hi[(size_t)Bn * Hh];
__device__ __align__(16) __half g_h1_lo[(size_t)Bn * Hh];
__device__ __align__(16) __half g_w0t[(size_t)Hh * INPAD2];   // [n][k] fp16
__device__ __align__(16) __half g_wht[4 * (size_t)Hh * Hh];   // [l][n][k] fp16
__device__ __align__(16) float g_bias[Ll * Hh];

// ---------------------------------------------------------------------------
// PTX helpers (base-arch: cp.async sm_80, ldmatrix sm_75, mma f16 sm_80)
// ---------------------------------------------------------------------------
__device__ __forceinline__ uint32_t smem_u32(const void* p) {
    uint32_t a;
    asm("{ .reg .u64 t; cvta.to.shared.u64 t, %1; cvt.u32.u64 %0, t; }"
        : "=r"(a) : "l"(p));
    return a;
}
__device__ __forceinline__ void cp16(uint32_t s, const void* g) {
    asm volatile("cp.async.cg.shared.global [%0], [%1], 16;" :: "r"(s), "l"(g));
}
#define CP_COMMIT() asm volatile("cp.async.commit_group;" ::: "memory")
#define CP_WAIT1()  asm volatile("cp.async.wait_group 1;" ::: "memory")

__device__ __forceinline__ void ldsm4(uint32_t* r, uint32_t addr) {
    asm volatile("ldmatrix.sync.aligned.m8n8.x4.shared.b16 {%0,%1,%2,%3}, [%4];"
        : "=r"(r[0]), "=r"(r[1]), "=r"(r[2]), "=r"(r[3]) : "r"(addr));
}
__device__ __forceinline__ void mma16816(float* d, const uint32_t* a,
                                         uint32_t b0, uint32_t b1) {
    asm volatile(
        "mma.sync.aligned.m16n8k16.row.col.f32.f16.f16.f32 "
        "{%0,%1,%2,%3}, {%4,%5,%6,%7}, {%8,%9}, {%0,%1,%2,%3};"
        : "+f"(d[0]), "+f"(d[1]), "+f"(d[2]), "+f"(d[3])
        : "r"(a[0]), "r"(a[1]), "r"(a[2]), "r"(a[3]), "r"(b0), "r"(b1));
}

// 128B-row SW128 swizzle: tile row (0..127), 16B unit u (0..7)
__device__ __forceinline__ uint32_t sw_addr(uint32_t base, int row, int u) {
    return base + (uint32_t)(row * 128) + (uint32_t)((u ^ (row & 7)) << 4);
}

// ---------------------------------------------------------------------------
// Setup: VQ (idx, loss, z_q_sum) + fold betas into per-layer biases.
// ---------------------------------------------------------------------------
__global__ void setup_kernel(const int* __restrict__ latent_idx,
                             const float* __restrict__ latents,
                             const float* __restrict__ codebooks,
                             const float* __restrict__ mod_W,
                             const float* __restrict__ mod_b,
                             const float* __restrict__ dec_b0,
                             const float* __restrict__ dec_bh,
                             float* __restrict__ out, int out_size)
{
    __shared__ float s_zqsum[Dd];
    __shared__ float s_res[Dd];
    __shared__ float s_zcur[Dd];
    __shared__ float s_dist[Kk];
    __shared__ int   s_idx[Kk];
    __shared__ float s_loss;
    __shared__ int   s_best[Ss];

    int tid = threadIdx.x;
    const float* img = latents + (size_t)(*latent_idx) * (Ss * Dd);

    if (tid < Dd) { s_zqsum[tid] = 0.f; s_res[tid] = 0.f; }
    if (tid == 0) s_loss = 0.f;
    __syncthreads();

    for (int s = 0; s < Ss; ++s) {
        if (tid < Dd) {
            float zs = img[s * Dd + tid];
            float rt = s_res[tid] + zs;
            s_res[tid] = rt;
            s_zcur[tid] = (s == 0) ? zs : (rt - s_zqsum[tid]);
        }
        __syncthreads();
        {
            const float* e = codebooks + ((size_t)s * Kk + tid) * Dd;
            float zz = 0.f, ee = 0.f, ze = 0.f;
            for (int d = 0; d < Dd; ++d) {
                float z = s_zcur[d], ev = e[d];
                zz += z * z; ee += ev * ev; ze += z * ev;
            }
            s_dist[tid] = zz - 2.f * ze + ee;
            s_idx[tid] = tid;
        }
        __syncthreads();
        for (int stride = Kk / 2; stride > 0; stride >>= 1) {
            if (tid < stride) {
                float d2 = s_dist[tid + stride];
                float d1 = s_dist[tid];
                int   i2 = s_idx[tid + stride];
                if (d2 < d1 || (d2 == d1 && i2 < s_idx[tid])) {
                    s_dist[tid] = d2; s_idx[tid] = i2;
                }
            }
            __syncthreads();
        }
        int best = s_idx[0];
        if (tid == 0) {
            const float* e = codebooks + ((size_t)s * Kk + best) * Dd;
            float acc = 0.f;
            for (int d = 0; d < Dd; ++d) { float df = e[d] - s_zcur[d]; acc += df * df; }
            s_loss += 0.25f * (acc / (float)Dd);
            s_best[s] = best;
        }
        if (tid < Dd) {
            const float* e = codebooks + ((size_t)s * Kk + best) * Dd;
            float zq = e[tid];
            float zqst = zq + (s_zcur[tid] - zq);
            s_zqsum[tid] += zqst;
        }
        __syncthreads();
    }

    for (int l = 0; l < Ll; ++l) {
        float acc = mod_b[l * Hh + tid];
        const float* w = mod_W + (size_t)l * Dd * Hh + tid;
        #pragma unroll 4
        for (int d = 0; d < Dd; ++d) acc += s_zqsum[d] * w[(size_t)d * Hh];
        acc += (l == 0) ? dec_b0[tid] : dec_bh[(l - 1) * Hh + tid];
        g_bias[l * Hh + tid] = acc;
    }

    const int base = Bn * Vv;
    if (out_size >= base + Ss + 1) {
        if (tid < Ss) out[base + tid] = (float)s_best[tid];
        if (tid == 0) out[base + Ss] = s_loss;
    }
}

// ---------------------------------------------------------------------------
// Positional encoding -> hi/lo fp16, padded to 128 cols.
// ---------------------------------------------------------------------------
__global__ void pe_kernel(const float* __restrict__ coords)
{
    int idx = blockIdx.x * blockDim.x + threadIdx.x;
    if (idx >= Bn * INPAD2) return;
    int b = idx >> 7, j = idx & 127;
    float v = 0.f;
    if (j < Cc) {
        v = coords[b * Cc + j];
    } else if (j < INDIM) {
        int r = j - Cc;
        int f = r >> 2, t = r & 3;
        int which = t >> 1, c = t & 1;
        float pf = exp2f((float)f) * 3.14159274101257324f;
        float ang = coords[b * Cc + c] * pf;
        double a = (double)ang;
        v = (float)((which == 0) ? sin(a) : cos(a));
    }
    __half h = __float2half_rn(v);
    g_pe_hi[idx] = h;
    g_pe_lo[idx] = __float2half_rn(v - __half2float(h));
}

// Transpose dec_W0 [K=102(->128), N=1024] -> g_w0t [n][k] fp16
__global__ void w0t_kernel(const float* __restrict__ W0)
{
    int idx = blockIdx.x * blockDim.x + threadIdx.x;
    if (idx >= Hh * INPAD2) return;
    int n = idx >> 7, k = idx & 127;
    float v = (k < INDIM) ? W0[(size_t)k * Hh + n] : 0.f;
    g_w0t[idx] = __float2half_rn(v);
}

// Transpose dec_Wh [4][K=1024][N=1024] -> g_wht [l][n][k] fp16
__global__ void wht_kernel(const float* __restrict__ Wh)
{
    size_t idx = (size_t)blockIdx.x * blockDim.x + threadIdx.x;
    if (idx >= 4 * (size_t)Hh * Hh) return;
    size_t l = idx >> 20;
    int n = (int)((idx >> 10) & 1023);
    int k = (int)(idx & 1023);
    g_wht[idx] = __float2half_rn(Wh[l * Hh * Hh + (size_t)k * Hh + n]);
}

// ---------------------------------------------------------------------------
// fp16 2-term GEMM via mma.sync: C = relu(A@W + bias)
// A = Ah + Al (fp16 pair, 22-bit), W = fp16 single.
// C = Ah*B + Al*B  (fp32 accumulate) == A@W up to B's fp16 rounding (~1.4e-4)
// Tile: CTA 128x128, BK=64, 4 warps (warp tile 64x64), 2-stage cp.async.
// Regions per stage: Ah / Al / B, each 128 rows x 128B (64 fp16), SW128.
// B stored [n][k] K-major -> B fragments via PLAIN ldmatrix (non-trans).
// ---------------------------------------------------------------------------
__global__ __launch_bounds__(128, 2)
void gemm_mma_kernel(int a_sel, int w_sel, int bias_l, int out_sel, int K)
{
    extern __shared__ char dsm[];

    const __half *Ahi, *Alo, *Bw;
    if (a_sel == 0)      { Ahi = g_pe_hi; Alo = g_pe_lo; }
    else if (a_sel == 1) { Ahi = g_h0_hi; Alo = g_h0_lo; }
    else                 { Ahi = g_h1_hi; Alo = g_h1_lo; }
    if (w_sel < 0) Bw = g_w0t;
    else           Bw = g_wht + (size_t)w_sel * Hh * Hh;
    __half* Ohi = (out_sel == 0) ? g_h0_hi : g_h1_hi;
    __half* Olo = (out_sel == 0) ? g_h0_lo : g_h1_lo;

    const int tid  = threadIdx.x;
    const int wid  = tid >> 5;
    const int lane = tid & 31;
    const int wm = wid >> 1;          // 0..1 (M: rows wm*64..+63)
    const int wn = wid & 1;           // 0..1 (N: cols wn*64..+63)
    const int n0 = blockIdx.x * BN;
    const size_t m0 = (size_t)blockIdx.y * BM;

    const uint32_t sbase = smem_u32(dsm);

    float acc[4][8][4];
    #pragma unroll
    for (int i = 0; i < 4; ++i)
        #pragma unroll
        for (int j = 0; j < 8; ++j)
            #pragma unroll
            for (int q = 0; q < 4; ++q) acc[i][j][q] = 0.f;

    const int nkt = K / BK;          // >= 2 always (L0: 2, hidden: 16)

    // ---- tile loader: 3 regions x 1024 cp16 = 24 cp16 per thread ----
    #define LOAD_STAGE(stg, kc) do {                                          \
        uint32_t bs = sbase + (stg) * STG_BYTES;                               \
        _Pragma("unroll")                                                      \
        for (int j = 0; j < 8; ++j) {                                          \
            int i = tid + j * 128;                                             \
            int row = i >> 3, u = i & 7;                                       \
            uint32_t dst = sw_addr(0, row, u);                                 \
            cp16(bs + OFF_AH + dst, Ahi + (m0 + row) * K + (kc) + u * 8);      \
            cp16(bs + OFF_AL + dst, Alo + (m0 + row) * K + (kc) + u * 8);      \
            cp16(bs + OFF_B  + dst, Bw + (size_t)(n0 + row) * K + (kc) + u * 8);\
        }                                                                      \
    } while (0)

    // prologue: stages 0 and 1
    LOAD_STAGE(0, 0);
    CP_COMMIT();
    LOAD_STAGE(1, BK);
    CP_COMMIT();

    const int lr = lane & 15;
    const int lh = lane >> 4;

    for (int c = 0; c < nkt; ++c) {
        // commits so far: (c+2). wait_group(1) -> commits 1..(c+1) complete,
        // i.e. stage c's data is resident. Sync makes it CTA-wide.
        CP_WAIT1();
        __syncthreads();

        uint32_t sA = sbase + (c & 1) * STG_BYTES;

        #pragma unroll
        for (int ks = 0; ks < 4; ++ks) {
            uint32_t af[4][4], bb[4][4];
            int uu = ks * 2 + lh;
            // A hi fragments
            #pragma unroll
            for (int mt = 0; mt < 4; ++mt)
                ldsm4(af[mt], sw_addr(sA + OFF_AH, wm * 64 + mt * 16 + lr, uu));
            // B fragments (non-trans: [n][k] rows give col-major B fragment)
            #pragma unroll
            for (int g = 0; g < 4; ++g)
                ldsm4(bb[g], sw_addr(sA + OFF_B, wn * 64 + g * 16 + lr, uu));
            // Ah * B
            #pragma unroll
            for (int mt = 0; mt < 4; ++mt)
                #pragma unroll
                for (int nt = 0; nt < 8; ++nt)
                    mma16816(acc[mt][nt], af[mt],
                             bb[nt >> 1][nt & 1], bb[nt >> 1][2 + (nt & 1)]);
            // A lo fragments (reuse af)
            #pragma unroll
            for (int mt = 0; mt < 4; ++mt)
                ldsm4(af[mt], sw_addr(sA + OFF_AL, wm * 64 + mt * 16 + lr, uu));
            // Al * B
            #pragma unroll
            for (int mt = 0; mt < 4; ++mt)
                #pragma unroll
                for (int nt = 0; nt < 8; ++nt)
                    mma16816(acc[mt][nt], af[mt],
                             bb[nt >> 1][nt & 1], bb[nt >> 1][2 + (nt & 1)]);
        }
        // all warps done reading stage c%2 before overwriting it
        __syncthreads();
        if (c + 2 < nkt) LOAD_STAGE(c & 1, (c + 2) * BK);
        CP_COMMIT();   // always commit (possibly empty) to keep group count uniform
    }
    #undef LOAD_STAGE

    // ---- epilogue: bias + relu + hi/lo split stores ----
    const float* bias = g_bias + bias_l * Hh + n0 + wn * 64;
    const int qr = lane >> 2;          // 0..7
    const int qc = (lane & 3) * 2;     // 0,2,4,6

    #pragma unroll
    for (int mt = 0; mt < 4; ++mt) {
        size_t r0 = m0 + wm * 64 + mt * 16 + qr;
        size_t r1 = r0 + 8;
        #pragma unroll
        for (int nt = 0; nt < 8; ++nt) {
            int cl = nt * 8 + qc;
            int col = n0 + wn * 64 + cl;
            float b0 = bias[cl], b1 = bias[cl + 1];
            float v00 = fmaxf(acc[mt][nt][0] + b0, 0.f);
            float v01 = fmaxf(acc[mt][nt][1] + b1, 0.f);
            float v10 = fmaxf(acc[mt][nt][2] + b0, 0.f);
            float v11 = fmaxf(acc[mt][nt][3] + b1, 0.f);
            __half h00 = __float2half_rn(v00);
            __half h01 = __float2half_rn(v01);
            __half h10 = __float2half_rn(v10);
            __half h11 = __float2half_rn(v11);
            *(__half2*)(Ohi + r0 * Hh + col) = __halves2half2(h00, h01);
            *(__half2*)(Ohi + r1 * Hh + col) = __halves2half2(h10, h11);
            *(__half2*)(Olo + r0 * Hh + col) = __halves2half2(
                __float2half_rn(v00 - __half2float(h00)),
                __float2half_rn(v01 - __half2float(h01)));
            *(__half2*)(Olo + r1 * Hh + col) = __halves2half2(
                __float2half_rn(v10 - __half2float(h10)),
                __float2half_rn(v11 - __half2float(h11)));
        }
    }
}

// ---------------------------------------------------------------------------
// Output projection: values[B,3] = (h_hi+h_lo) @ Wout + bout. One warp/row.
// ---------------------------------------------------------------------------
__global__ void out_kernel(const float* __restrict__ Wout,
                           const float* __restrict__ bout,
                           float* __restrict__ out)
{
    int gwarp = (blockIdx.x * blockDim.x + threadIdx.x) >> 5;
    int lane = threadIdx.x & 31;
    if (gwarp >= Bn) return;
    const __half* hh = g_h0_hi + (size_t)gwarp * Hh;
    const __half* hl = g_h0_lo + (size_t)gwarp * Hh;
    float a0 = 0.f, a1 = 0.f, a2 = 0.f;
    #pragma unroll 4
    for (int i = 0; i < 16; ++i) {
        int k = i * 64 + lane * 2;
        __half2 vh = *(const __half2*)(hh + k);
        __half2 vl = *(const __half2*)(hl + k);
        float h0 = __half2float(__low2half(vh)) + __half2float(__low2half(vl));
        float h1 = __half2float(__high2half(vh)) + __half2float(__high2half(vl));
        a0 += h0 * Wout[k * 3 + 0] + h1 * Wout[(k + 1) * 3 + 0];
        a1 += h0 * Wout[k * 3 + 1] + h1 * Wout[(k + 1) * 3 + 1];
        a2 += h0 * Wout[k * 3 + 2] + h1 * Wout[(k + 1) * 3 + 2];
    }
    #pragma unroll
    for (int off = 16; off; off >>= 1) {
        a0 += __shfl_down_sync(0xffffffffu, a0, off);
        a1 += __shfl_down_sync(0xffffffffu, a1, off);
        a2 += __shfl_down_sync(0xffffffffu, a2, off);
    }
    if (lane == 0) {
        out[gwarp * 3 + 0] = a0 + bout[0];
        out[gwarp * 3 + 1] = a1 + bout[1];
        out[gwarp * 3 + 2] = a2 + bout[2];
    }
}

// ---------------------------------------------------------------------------
extern "C" void kernel_launch(void* const* d_in, const int* in_sizes, int n_in,
                              void* d_out, int out_size)
{
    const float* coords     = (const float*)d_in[0];
    const int*   latent_idx = (const int*)  d_in[1];
    const float* latents    = (const float*)d_in[2];
    const float* codebooks  = (const float*)d_in[3];
    const float* mod_W      = (const float*)d_in[4];
    const float* mod_b      = (const float*)d_in[5];
    const float* dec_W0     = (const float*)d_in[6];
    const float* dec_b0     = (const float*)d_in[7];
    const float* dec_Wh     = (const float*)d_in[8];
    const float* dec_bh     = (const float*)d_in[9];
    const float* dec_Wout   = (const float*)d_in[10];
    const float* dec_bout   = (const float*)d_in[11];
    float* out = (float*)d_out;

    cudaFuncSetAttribute(gemm_mma_kernel,
                         cudaFuncAttributeMaxDynamicSharedMemorySize, SMEM_DYN);

    setup_kernel<<<1, 1024>>>(latent_idx, latents, codebooks, mod_W, mod_b,
                              dec_b0, dec_bh, out, out_size);
    pe_kernel<<<(Bn * INPAD2 + 255) / 256, 256>>>(coords);
    w0t_kernel<<<(Hh * INPAD2 + 255) / 256, 256>>>(dec_W0);
    wht_kernel<<<(int)((4 * (size_t)Hh * Hh + 255) / 256), 256>>>(dec_Wh);

    dim3 grid(Hh / BN, Bn / BM);   // (8, 512)
    // L0: pe @ W0t -> h0
    gemm_mma_kernel<<<grid, 128, SMEM_DYN>>>(0, -1, 0, 0, INPAD2);
    // hidden layers ping-pong h0 <-> h1
    gemm_mma_kernel<<<grid, 128, SMEM_DYN>>>(1, 0, 1, 1, Hh);
    gemm_mma_kernel<<<grid, 128, SMEM_DYN>>>(2, 1, 2, 0, Hh);
    gemm_mma_kernel<<<grid, 128, SMEM_DYN>>>(1, 2, 3, 1, Hh);
    gemm_mma_kernel<<<grid, 128, SMEM_DYN>>>(2, 3, 4, 0, Hh);
    // output projection reads h0
    out_kernel<<<(Bn * 32 + 255) / 256, 256>>>(dec_Wout, dec_bout, out);
}

// round 15
// speedup vs baseline: 2.2065x; 1.4664x over previous
#include <cuda_runtime.h>
#include <cuda_fp16.h>
#include <math.h>
#include <stdint.h>

// Problem constants
#define Bn 65536
#define Cc 2
#define Vv 3
#define Dd 64
#define Kk 1024
#define Ss 4
#define Hh 1024
#define Ll 5
#define Ff 25
#define INDIM 102      // C*(2F+1)
#define INPAD2 128     // layer-0 K padded to 128

// GEMM tiling (mma.sync path, base sm_103 compatible)
#define BM 128
#define BN 128
#define BK 64
#define STAGES 2
#define STG_BYTES 49152          // Ah 16KB + Al 16KB + B 16KB
#define OFF_AH 0
#define OFF_AL 16384
#define OFF_B  32768
#define SMEM_DYN (STAGES * STG_BYTES)

// ---------------------------------------------------------------------------
// Device-global scratch (no allocations allowed)
// ---------------------------------------------------------------------------
__device__ __align__(16) __half g_pe_hi[(size_t)Bn * INPAD2];
__device__ __align__(16) __half g_pe_lo[(size_t)Bn * INPAD2];
__device__ __align__(16) __half g_h0[(size_t)Bn * Hh];        // activations, fp16
__device__ __align__(16) __half g_h1[(size_t)Bn * Hh];
__device__ __align__(16) __half g_w0t[(size_t)Hh * INPAD2];   // [n][k] fp16
__device__ __align__(16) __half g_wht[4 * (size_t)Hh * Hh];   // [l][n][k] fp16
__device__ __align__(16) float g_bias[Ll * Hh];

// ---------------------------------------------------------------------------
// PTX helpers (base-arch: cp.async sm_80, ldmatrix sm_75, mma f16 sm_80)
// ---------------------------------------------------------------------------
__device__ __forceinline__ uint32_t smem_u32(const void* p) {
    uint32_t a;
    asm("{ .reg .u64 t; cvta.to.shared.u64 t, %1; cvt.u32.u64 %0, t; }"
        : "=r"(a) : "l"(p));
    return a;
}
__device__ __forceinline__ void cp16(uint32_t s, const void* g) {
    asm volatile("cp.async.cg.shared.global [%0], [%1], 16;" :: "r"(s), "l"(g));
}
#define CP_COMMIT() asm volatile("cp.async.commit_group;" ::: "memory")
#define CP_WAIT1()  asm volatile("cp.async.wait_group 1;" ::: "memory")

__device__ __forceinline__ void ldsm4(uint32_t* r, uint32_t addr) {
    asm volatile("ldmatrix.sync.aligned.m8n8.x4.shared.b16 {%0,%1,%2,%3}, [%4];"
        : "=r"(r[0]), "=r"(r[1]), "=r"(r[2]), "=r"(r[3]) : "r"(addr));
}
__device__ __forceinline__ void mma16816(float* d, const uint32_t* a,
                                         uint32_t b0, uint32_t b1) {
    asm volatile(
        "mma.sync.aligned.m16n8k16.row.col.f32.f16.f16.f32 "
        "{%0,%1,%2,%3}, {%4,%5,%6,%7}, {%8,%9}, {%0,%1,%2,%3};"
        : "+f"(d[0]), "+f"(d[1]), "+f"(d[2]), "+f"(d[3])
        : "r"(a[0]), "r"(a[1]), "r"(a[2]), "r"(a[3]), "r"(b0), "r"(b1));
}

// 128B-row SW128 swizzle: tile row (0..127), 16B unit u (0..7)
__device__ __forceinline__ uint32_t sw_addr(uint32_t base, int row, int u) {
    return base + (uint32_t)(row * 128) + (uint32_t)((u ^ (row & 7)) << 4);
}

// ---------------------------------------------------------------------------
// Setup: VQ (idx, loss, z_q_sum) + fold betas into per-layer biases.
// ---------------------------------------------------------------------------
__global__ void setup_kernel(const int* __restrict__ latent_idx,
                             const float* __restrict__ latents,
                             const float* __restrict__ codebooks,
                             const float* __restrict__ mod_W,
                             const float* __restrict__ mod_b,
                             const float* __restrict__ dec_b0,
                             const float* __restrict__ dec_bh,
                             float* __restrict__ out, int out_size)
{
    __shared__ float s_zqsum[Dd];
    __shared__ float s_res[Dd];
    __shared__ float s_zcur[Dd];
    __shared__ float s_dist[Kk];
    __shared__ int   s_idx[Kk];
    __shared__ float s_loss;
    __shared__ int   s_best[Ss];

    int tid = threadIdx.x;
    const float* img = latents + (size_t)(*latent_idx) * (Ss * Dd);

    if (tid < Dd) { s_zqsum[tid] = 0.f; s_res[tid] = 0.f; }
    if (tid == 0) s_loss = 0.f;
    __syncthreads();

    for (int s = 0; s < Ss; ++s) {
        if (tid < Dd) {
            float zs = img[s * Dd + tid];
            float rt = s_res[tid] + zs;
            s_res[tid] = rt;
            s_zcur[tid] = (s == 0) ? zs : (rt - s_zqsum[tid]);
        }
        __syncthreads();
        {
            const float* e = codebooks + ((size_t)s * Kk + tid) * Dd;
            float zz = 0.f, ee = 0.f, ze = 0.f;
            for (int d = 0; d < Dd; ++d) {
                float z = s_zcur[d], ev = e[d];
                zz += z * z; ee += ev * ev; ze += z * ev;
            }
            s_dist[tid] = zz - 2.f * ze + ee;
            s_idx[tid] = tid;
        }
        __syncthreads();
        for (int stride = Kk / 2; stride > 0; stride >>= 1) {
            if (tid < stride) {
                float d2 = s_dist[tid + stride];
                float d1 = s_dist[tid];
                int   i2 = s_idx[tid + stride];
                if (d2 < d1 || (d2 == d1 && i2 < s_idx[tid])) {
                    s_dist[tid] = d2; s_idx[tid] = i2;
                }
            }
            __syncthreads();
        }
        int best = s_idx[0];
        if (tid == 0) {
            const float* e = codebooks + ((size_t)s * Kk + best) * Dd;
            float acc = 0.f;
            for (int d = 0; d < Dd; ++d) { float df = e[d] - s_zcur[d]; acc += df * df; }
            s_loss += 0.25f * (acc / (float)Dd);
            s_best[s] = best;
        }
        if (tid < Dd) {
            const float* e = codebooks + ((size_t)s * Kk + best) * Dd;
            float zq = e[tid];
            float zqst = zq + (s_zcur[tid] - zq);
            s_zqsum[tid] += zqst;
        }
        __syncthreads();
    }

    for (int l = 0; l < Ll; ++l) {
        float acc = mod_b[l * Hh + tid];
        const float* w = mod_W + (size_t)l * Dd * Hh + tid;
        #pragma unroll 4
        for (int d = 0; d < Dd; ++d) acc += s_zqsum[d] * w[(size_t)d * Hh];
        acc += (l == 0) ? dec_b0[tid] : dec_bh[(l - 1) * Hh + tid];
        g_bias[l * Hh + tid] = acc;
    }

    const int base = Bn * Vv;
    if (out_size >= base + Ss + 1) {
        if (tid < Ss) out[base + tid] = (float)s_best[tid];
        if (tid == 0) out[base + Ss] = s_loss;
    }
}

// ---------------------------------------------------------------------------
// Positional encoding -> hi/lo fp16, padded to 128 cols.
// ---------------------------------------------------------------------------
__global__ void pe_kernel(const float* __restrict__ coords)
{
    int idx = blockIdx.x * blockDim.x + threadIdx.x;
    if (idx >= Bn * INPAD2) return;
    int b = idx >> 7, j = idx & 127;
    float v = 0.f;
    if (j < Cc) {
        v = coords[b * Cc + j];
    } else if (j < INDIM) {
        int r = j - Cc;
        int f = r >> 2, t = r & 3;
        int which = t >> 1, c = t & 1;
        float pf = exp2f((float)f) * 3.14159274101257324f;
        float ang = coords[b * Cc + c] * pf;
        double a = (double)ang;
        v = (float)((which == 0) ? sin(a) : cos(a));
    }
    __half h = __float2half_rn(v);
    g_pe_hi[idx] = h;
    g_pe_lo[idx] = __float2half_rn(v - __half2float(h));
}

// Transpose dec_W0 [K=102(->128), N=1024] -> g_w0t [n][k] fp16
__global__ void w0t_kernel(const float* __restrict__ W0)
{
    int idx = blockIdx.x * blockDim.x + threadIdx.x;
    if (idx >= Hh * INPAD2) return;
    int n = idx >> 7, k = idx & 127;
    float v = (k < INDIM) ? W0[(size_t)k * Hh + n] : 0.f;
    g_w0t[idx] = __float2half_rn(v);
}

// Transpose dec_Wh [4][K=1024][N=1024] -> g_wht [l][n][k] fp16
__global__ void wht_kernel(const float* __restrict__ Wh)
{
    size_t idx = (size_t)blockIdx.x * blockDim.x + threadIdx.x;
    if (idx >= 4 * (size_t)Hh * Hh) return;
    size_t l = idx >> 20;
    int n = (int)((idx >> 10) & 1023);
    int k = (int)(idx & 1023);
    g_wht[idx] = __float2half_rn(Wh[l * Hh * Hh + (size_t)k * Hh + n]);
}

// ---------------------------------------------------------------------------
// fp16 GEMM via mma.sync: C = relu(A@W + bias)
// Layer 0 (a_sel==0): A = Ah + Al (fp16 pair, 22-bit) -> 2 MMA terms.
// Hidden layers:      A = single fp16 -> 1 MMA term (activations are fp16;
//                     their rounding adds ~2e-4 rel per tensor, budgeted).
// W = fp16 single always (adds ~1.4e-4 over 5 layers, validated R14).
// Tile: CTA 128x128, BK=64, 4 warps (warp tile 64x64), 2-stage cp.async.
// Regions per stage: Ah / (Al) / B, each 128 rows x 128B (64 fp16), SW128.
// B stored [n][k] K-major -> B fragments via PLAIN ldmatrix (non-trans).
// ---------------------------------------------------------------------------
__global__ __launch_bounds__(128, 2)
void gemm_mma_kernel(int a_sel, int w_sel, int bias_l, int out_sel, int K)
{
    extern __shared__ char dsm[];

    const bool twoterm = (a_sel == 0);
    const __half *Ahi, *Alo, *Bw;
    if (a_sel == 0)      { Ahi = g_pe_hi; Alo = g_pe_lo; }
    else if (a_sel == 1) { Ahi = g_h0; Alo = g_h0; }
    else                 { Ahi = g_h1; Alo = g_h1; }
    if (w_sel < 0) Bw = g_w0t;
    else           Bw = g_wht + (size_t)w_sel * Hh * Hh;
    __half* Oh = (out_sel == 0) ? g_h0 : g_h1;

    const int tid  = threadIdx.x;
    const int wid  = tid >> 5;
    const int lane = tid & 31;
    const int wm = wid >> 1;          // 0..1 (M: rows wm*64..+63)
    const int wn = wid & 1;           // 0..1 (N: cols wn*64..+63)
    const int n0 = blockIdx.x * BN;
    const size_t m0 = (size_t)blockIdx.y * BM;

    const uint32_t sbase = smem_u32(dsm);

    float acc[4][8][4];
    #pragma unroll
    for (int i = 0; i < 4; ++i)
        #pragma unroll
        for (int j = 0; j < 8; ++j)
            #pragma unroll
            for (int q = 0; q < 4; ++q) acc[i][j][q] = 0.f;

    const int nkt = K / BK;          // L0: 2, hidden: 16

    // ---- tile loader: Ah + B (+ Al when twoterm), 16-24 cp16 per thread ----
    #define LOAD_STAGE(stg, kc) do {                                          \
        uint32_t bs = sbase + (stg) * STG_BYTES;                               \
        _Pragma("unroll")                                                      \
        for (int j = 0; j < 8; ++j) {                                          \
            int i = tid + j * 128;                                             \
            int row = i >> 3, u = i & 7;                                       \
            uint32_t dst = sw_addr(0, row, u);                                 \
            cp16(bs + OFF_AH + dst, Ahi + (m0 + row) * K + (kc) + u * 8);      \
            if (twoterm)                                                       \
                cp16(bs + OFF_AL + dst, Alo + (m0 + row) * K + (kc) + u * 8);  \
            cp16(bs + OFF_B  + dst, Bw + (size_t)(n0 + row) * K + (kc) + u * 8);\
        }                                                                      \
    } while (0)

    // prologue: stages 0 and 1
    LOAD_STAGE(0, 0);
    CP_COMMIT();
    LOAD_STAGE(1, BK);
    CP_COMMIT();

    const int lr = lane & 15;
    const int lh = lane >> 4;

    for (int c = 0; c < nkt; ++c) {
        // commits so far: (c+2). wait_group(1) -> commits 1..(c+1) complete,
        // i.e. stage c's data is resident. Sync makes it CTA-wide.
        CP_WAIT1();
        __syncthreads();

        uint32_t sA = sbase + (c & 1) * STG_BYTES;

        #pragma unroll
        for (int ks = 0; ks < 4; ++ks) {
            uint32_t af[4][4], bb[4][4];
            int uu = ks * 2 + lh;
            // A hi fragments
            #pragma unroll
            for (int mt = 0; mt < 4; ++mt)
                ldsm4(af[mt], sw_addr(sA + OFF_AH, wm * 64 + mt * 16 + lr, uu));
            // B fragments (non-trans: [n][k] rows give col-major B fragment)
            #pragma unroll
            for (int g = 0; g < 4; ++g)
                ldsm4(bb[g], sw_addr(sA + OFF_B, wn * 64 + g * 16 + lr, uu));
            // Ah * B
            #pragma unroll
            for (int mt = 0; mt < 4; ++mt)
                #pragma unroll
                for (int nt = 0; nt < 8; ++nt)
                    mma16816(acc[mt][nt], af[mt],
                             bb[nt >> 1][nt & 1], bb[nt >> 1][2 + (nt & 1)]);
            if (twoterm) {
                // A lo fragments (reuse af)
                #pragma unroll
                for (int mt = 0; mt < 4; ++mt)
                    ldsm4(af[mt], sw_addr(sA + OFF_AL, wm * 64 + mt * 16 + lr, uu));
                // Al * B
                #pragma unroll
                for (int mt = 0; mt < 4; ++mt)
                    #pragma unroll
                    for (int nt = 0; nt < 8; ++nt)
                        mma16816(acc[mt][nt], af[mt],
                                 bb[nt >> 1][nt & 1], bb[nt >> 1][2 + (nt & 1)]);
            }
        }
        // all warps done reading stage c%2 before overwriting it
        __syncthreads();
        if (c + 2 < nkt) LOAD_STAGE(c & 1, (c + 2) * BK);
        CP_COMMIT();   // always commit (possibly empty) to keep group count uniform
    }
    #undef LOAD_STAGE

    // ---- epilogue: bias + relu + fp16 stores ----
    const float* bias = g_bias + bias_l * Hh + n0 + wn * 64;
    const int qr = lane >> 2;          // 0..7
    const int qc = (lane & 3) * 2;     // 0,2,4,6

    #pragma unroll
    for (int mt = 0; mt < 4; ++mt) {
        size_t r0 = m0 + wm * 64 + mt * 16 + qr;
        size_t r1 = r0 + 8;
        #pragma unroll
        for (int nt = 0; nt < 8; ++nt) {
            int cl = nt * 8 + qc;
            int col = n0 + wn * 64 + cl;
            float b0 = bias[cl], b1 = bias[cl + 1];
            float v00 = fmaxf(acc[mt][nt][0] + b0, 0.f);
            float v01 = fmaxf(acc[mt][nt][1] + b1, 0.f);
            float v10 = fmaxf(acc[mt][nt][2] + b0, 0.f);
            float v11 = fmaxf(acc[mt][nt][3] + b1, 0.f);
            *(__half2*)(Oh + r0 * Hh + col) =
                __halves2half2(__float2half_rn(v00), __float2half_rn(v01));
            *(__half2*)(Oh + r1 * Hh + col) =
                __halves2half2(__float2half_rn(v10), __float2half_rn(v11));
        }
    }
}

// ---------------------------------------------------------------------------
// Output projection: values[B,3] = h @ Wout + bout. One warp/row.
// ---------------------------------------------------------------------------
__global__ void out_kernel(const float* __restrict__ Wout,
                           const float* __restrict__ bout,
                           float* __restrict__ out)
{
    int gwarp = (blockIdx.x * blockDim.x + threadIdx.x) >> 5;
    int lane = threadIdx.x & 31;
    if (gwarp >= Bn) return;
    const __half* hh = g_h0 + (size_t)gwarp * Hh;
    float a0 = 0.f, a1 = 0.f, a2 = 0.f;
    #pragma unroll 4
    for (int i = 0; i < 16; ++i) {
        int k = i * 64 + lane * 2;
        __half2 vh = *(const __half2*)(hh + k);
        float h0 = __half2float(__low2half(vh));
        float h1 = __half2float(__high2half(vh));
        a0 += h0 * Wout[k * 3 + 0] + h1 * Wout[(k + 1) * 3 + 0];
        a1 += h0 * Wout[k * 3 + 1] + h1 * Wout[(k + 1) * 3 + 1];
        a2 += h0 * Wout[k * 3 + 2] + h1 * Wout[(k + 1) * 3 + 2];
    }
    #pragma unroll
    for (int off = 16; off; off >>= 1) {
        a0 += __shfl_down_sync(0xffffffffu, a0, off);
        a1 += __shfl_down_sync(0xffffffffu, a1, off);
        a2 += __shfl_down_sync(0xffffffffu, a2, off);
    }
    if (lane == 0) {
        out[gwarp * 3 + 0] = a0 + bout[0];
        out[gwarp * 3 + 1] = a1 + bout[1];
        out[gwarp * 3 + 2] = a2 + bout[2];
    }
}

// ---------------------------------------------------------------------------
extern "C" void kernel_launch(void* const* d_in, const int* in_sizes, int n_in,
                              void* d_out, int out_size)
{
    const float* coords     = (const float*)d_in[0];
    const int*   latent_idx = (const int*)  d_in[1];
    const float* latents    = (const float*)d_in[2];
    const float* codebooks  = (const float*)d_in[3];
    const float* mod_W      = (const float*)d_in[4];
    const float* mod_b      = (const float*)d_in[5];
    const float* dec_W0     = (const float*)d_in[6];
    const float* dec_b0     = (const float*)d_in[7];
    const float* dec_Wh     = (const float*)d_in[8];
    const float* dec_bh     = (const float*)d_in[9];
    const float* dec_Wout   = (const float*)d_in[10];
    const float* dec_bout   = (const float*)d_in[11];
    float* out = (float*)d_out;

    cudaFuncSetAttribute(gemm_mma_kernel,
                         cudaFuncAttributeMaxDynamicSharedMemorySize, SMEM_DYN);

    setup_kernel<<<1, 1024>>>(latent_idx, latents, codebooks, mod_W, mod_b,
                              dec_b0, dec_bh, out, out_size);
    pe_kernel<<<(Bn * INPAD2 + 255) / 256, 256>>>(coords);
    w0t_kernel<<<(Hh * INPAD2 + 255) / 256, 256>>>(dec_W0);
    wht_kernel<<<(int)((4 * (size_t)Hh * Hh + 255) / 256), 256>>>(dec_Wh);

    dim3 grid(Hh / BN, Bn / BM);   // (8, 512)
    // L0: pe @ W0t -> h0 (2-term: pe hi+lo)
    gemm_mma_kernel<<<grid, 128, SMEM_DYN>>>(0, -1, 0, 0, INPAD2);
    // hidden layers ping-pong h0 <-> h1 (1-term fp16)
    gemm_mma_kernel<<<grid, 128, SMEM_DYN>>>(1, 0, 1, 1, Hh);
    gemm_mma_kernel<<<grid, 128, SMEM_DYN>>>(2, 1, 2, 0, Hh);
    gemm_mma_kernel<<<grid, 128, SMEM_DYN>>>(1, 2, 3, 1, Hh);
    gemm_mma_kernel<<<grid, 128, SMEM_DYN>>>(2, 3, 4, 0, Hh);
    // output projection reads h0
    out_kernel<<<(Bn * 32 + 255) / 256, 256>>>(dec_Wout, dec_bout, out);
}

// round 16
// speedup vs baseline: 2.7767x; 1.2584x over previous
#include <cuda_runtime.h>
#include <cuda_fp16.h>
#include <math.h>
#include <stdint.h>

// Problem constants
#define Bn 65536
#define Cc 2
#define Vv 3
#define Dd 64
#define Kk 1024
#define Ss 4
#define Hh 1024
#define Ll 5
#define Ff 25
#define INDIM 102      // C*(2F+1)
#define INPAD2 128     // layer-0 K padded to 128

// GEMM tiling (mma.sync path, base sm_103 compatible)
#define BM 128
#define BN 128
#define BK 64
#define STAGES 2
#define STG_BYTES 49152          // Ah 16KB + Al 16KB + B 16KB
#define OFF_AH 0
#define OFF_AL 16384
#define OFF_B  32768
#define SMEM_DYN (STAGES * STG_BYTES)

// ---------------------------------------------------------------------------
// Device-global scratch (no allocations allowed)
// ---------------------------------------------------------------------------
__device__ __align__(16) __half g_pe_hi[(size_t)Bn * INPAD2];
__device__ __align__(16) __half g_pe_lo[(size_t)Bn * INPAD2];
__device__ __align__(16) __half g_h0[(size_t)Bn * Hh];        // activations, fp16
__device__ __align__(16) __half g_h1[(size_t)Bn * Hh];
__device__ __align__(16) __half g_w0t[(size_t)Hh * INPAD2];   // [n][k] fp16
__device__ __align__(16) __half g_wht[4 * (size_t)Hh * Hh];   // [l][n][k] fp16
__device__ __align__(16) float g_bias[Ll * Hh];
__device__ __align__(16) float g_zq[Dd];                      // z_q_sum from VQ

// ---------------------------------------------------------------------------
// PTX helpers (base-arch: cp.async sm_80, ldmatrix sm_75, mma f16 sm_80)
// ---------------------------------------------------------------------------
__device__ __forceinline__ uint32_t smem_u32(const void* p) {
    uint32_t a;
    asm("{ .reg .u64 t; cvta.to.shared.u64 t, %1; cvt.u32.u64 %0, t; }"
        : "=r"(a) : "l"(p));
    return a;
}
__device__ __forceinline__ void cp16(uint32_t s, const void* g) {
    asm volatile("cp.async.cg.shared.global [%0], [%1], 16;" :: "r"(s), "l"(g));
}
#define CP_COMMIT() asm volatile("cp.async.commit_group;" ::: "memory")
#define CP_WAIT1()  asm volatile("cp.async.wait_group 1;" ::: "memory")

__device__ __forceinline__ void ldsm4(uint32_t* r, uint32_t addr) {
    asm volatile("ldmatrix.sync.aligned.m8n8.x4.shared.b16 {%0,%1,%2,%3}, [%4];"
        : "=r"(r[0]), "=r"(r[1]), "=r"(r[2]), "=r"(r[3]) : "r"(addr));
}
__device__ __forceinline__ void mma16816(float* d, const uint32_t* a,
                                         uint32_t b0, uint32_t b1) {
    asm volatile(
        "mma.sync.aligned.m16n8k16.row.col.f32.f16.f16.f32 "
        "{%0,%1,%2,%3}, {%4,%5,%6,%7}, {%8,%9}, {%0,%1,%2,%3};"
        : "+f"(d[0]), "+f"(d[1]), "+f"(d[2]), "+f"(d[3])
        : "r"(a[0]), "r"(a[1]), "r"(a[2]), "r"(a[3]), "r"(b0), "r"(b1));
}

// 128B-row SW128 swizzle: tile row (0..127), 16B unit u (0..7)
__device__ __forceinline__ uint32_t sw_addr(uint32_t base, int row, int u) {
    return base + (uint32_t)(row * 128) + (uint32_t)((u ^ (row & 7)) << 4);
}

// ---------------------------------------------------------------------------
// Fast accurate sin/cos of an exact fp32 angle (|x| < 2^26).
// Double Cody-Waite quadrant reduction (4 DP ops, exact k*C1), fp32 minimax
// polys on |r|<=pi/4. Agreement with accurate f32 sin: ~1-2 ulp.
// ---------------------------------------------------------------------------
__device__ __forceinline__ float fast_trig(float x, int want_cos)
{
    const double TWO_OVER_PI = 0.636619772367581343075535;
    const double C1 = 1.57079637050628662109375;       // (double)(float)(pi/2), 24-bit
    const double C2 = -4.37113900018624283e-08;        // pi/2 - C1
    double d = (double)x;
    double k = rint(d * TWO_OVER_PI);
    double r = fma(-k, C1, d);
    r = fma(-k, C2, r);
    int q = ((int)k + want_cos) & 3;
    float rf = (float)r;
    float z = rf * rf;
    // sin poly on [-pi/4, pi/4]
    float ps = -1.9515295891e-4f;
    ps = fmaf(ps, z, 8.3321608736e-3f);
    ps = fmaf(ps, z, -1.6666654611e-1f);
    float s = fmaf(rf * z, ps, rf);
    // cos poly on [-pi/4, pi/4]
    float pc = 2.443315711809948e-5f;
    pc = fmaf(pc, z, -1.388731625493765e-3f);
    pc = fmaf(pc, z, 4.166664568298827e-2f);
    float c = fmaf(z * z, pc, fmaf(z, -0.5f, 1.0f));
    float v = (q & 1) ? c : s;
    return (q == 1 || q == 2) ? ((q & 1) ? -c : -s) * 0.f + ((q >> 1) ? -v : v)
                              : v;
}
// NOTE: the last line simplifies to: quadrants 2,3 negate. Rewritten clearly:
__device__ __forceinline__ float fast_trig2(float x, int want_cos)
{
    const double TWO_OVER_PI = 0.636619772367581343075535;
    const double C1 = 1.57079637050628662109375;
    const double C2 = -4.37113900018624283e-08;
    double d = (double)x;
    double k = rint(d * TWO_OVER_PI);
    double r = fma(-k, C1, d);
    r = fma(-k, C2, r);
    int q = ((int)k + want_cos) & 3;
    float rf = (float)r;
    float z = rf * rf;
    float ps = -1.9515295891e-4f;
    ps = fmaf(ps, z, 8.3321608736e-3f);
    ps = fmaf(ps, z, -1.6666654611e-1f);
    float s = fmaf(rf * z, ps, rf);
    float pc = 2.443315711809948e-5f;
    pc = fmaf(pc, z, -1.388731625493765e-3f);
    pc = fmaf(pc, z, 4.166664568298827e-2f);
    float c = fmaf(z * z, pc, fmaf(z, -0.5f, 1.0f));
    float v = (q & 1) ? c : s;
    return (q & 2) ? -v : v;
}

// ---------------------------------------------------------------------------
// Setup: VQ (idx, loss, z_q_sum). One CTA. Bias fold moved to bias_kernel.
// ---------------------------------------------------------------------------
__global__ void setup_kernel(const int* __restrict__ latent_idx,
                             const float* __restrict__ latents,
                             const float* __restrict__ codebooks,
                             float* __restrict__ out, int out_size)
{
    __shared__ float s_zqsum[Dd];
    __shared__ float s_res[Dd];
    __shared__ float s_zcur[Dd];
    __shared__ float s_dist[Kk];
    __shared__ int   s_idx[Kk];
    __shared__ float s_loss;
    __shared__ int   s_best[Ss];

    int tid = threadIdx.x;
    const float* img = latents + (size_t)(*latent_idx) * (Ss * Dd);

    if (tid < Dd) { s_zqsum[tid] = 0.f; s_res[tid] = 0.f; }
    if (tid == 0) s_loss = 0.f;
    __syncthreads();

    for (int s = 0; s < Ss; ++s) {
        if (tid < Dd) {
            float zs = img[s * Dd + tid];
            float rt = s_res[tid] + zs;
            s_res[tid] = rt;
            s_zcur[tid] = (s == 0) ? zs : (rt - s_zqsum[tid]);
        }
        __syncthreads();
        {
            const float* e = codebooks + ((size_t)s * Kk + tid) * Dd;
            float zz = 0.f, ee = 0.f, ze = 0.f;
            for (int d = 0; d < Dd; ++d) {
                float z = s_zcur[d], ev = e[d];
                zz += z * z; ee += ev * ev; ze += z * ev;
            }
            s_dist[tid] = zz - 2.f * ze + ee;
            s_idx[tid] = tid;
        }
        __syncthreads();
        for (int stride = Kk / 2; stride > 0; stride >>= 1) {
            if (tid < stride) {
                float d2 = s_dist[tid + stride];
                float d1 = s_dist[tid];
                int   i2 = s_idx[tid + stride];
                if (d2 < d1 || (d2 == d1 && i2 < s_idx[tid])) {
                    s_dist[tid] = d2; s_idx[tid] = i2;
                }
            }
            __syncthreads();
        }
        int best = s_idx[0];
        if (tid == 0) {
            const float* e = codebooks + ((size_t)s * Kk + best) * Dd;
            float acc = 0.f;
            for (int d = 0; d < Dd; ++d) { float df = e[d] - s_zcur[d]; acc += df * df; }
            s_loss += 0.25f * (acc / (float)Dd);
            s_best[s] = best;
        }
        if (tid < Dd) {
            const float* e = codebooks + ((size_t)s * Kk + best) * Dd;
            float zq = e[tid];
            float zqst = zq + (s_zcur[tid] - zq);
            s_zqsum[tid] += zqst;
        }
        __syncthreads();
    }

    if (tid < Dd) g_zq[tid] = s_zqsum[tid];

    const int base = Bn * Vv;
    if (out_size >= base + Ss + 1) {
        if (tid < Ss) out[base + tid] = (float)s_best[tid];
        if (tid == 0) out[base + Ss] = s_loss;
    }
}

// ---------------------------------------------------------------------------
// Bias fold (parallel): bias_l = mod_b[l] + zq @ mod_W[l] + dec_b_l
// Same accumulation order as the old in-setup fold -> bit-identical.
// ---------------------------------------------------------------------------
__global__ void bias_kernel(const float* __restrict__ mod_W,
                            const float* __restrict__ mod_b,
                            const float* __restrict__ dec_b0,
                            const float* __restrict__ dec_bh)
{
    int idx = blockIdx.x * blockDim.x + threadIdx.x;
    if (idx >= Ll * Hh) return;
    int l = idx >> 10, n = idx & 1023;
    float acc = mod_b[idx];
    const float* w = mod_W + (size_t)l * Dd * Hh + n;
    #pragma unroll 4
    for (int d = 0; d < Dd; ++d) acc += g_zq[d] * w[(size_t)d * Hh];
    acc += (l == 0) ? dec_b0[n] : dec_bh[(l - 1) * Hh + n];
    g_bias[idx] = acc;
}

// ---------------------------------------------------------------------------
// Positional encoding -> hi/lo fp16, padded to 128 cols. Fast trig.
// ---------------------------------------------------------------------------
__global__ void pe_kernel(const float* __restrict__ coords)
{
    int idx = blockIdx.x * blockDim.x + threadIdx.x;
    if (idx >= Bn * INPAD2) return;
    int b = idx >> 7, j = idx & 127;
    float v = 0.f;
    if (j < Cc) {
        v = coords[b * Cc + j];
    } else if (j < INDIM) {
        int r = j - Cc;
        int f = r >> 2, t = r & 3;
        int which = t >> 1, c = t & 1;
        float pf = exp2f((float)f) * 3.14159274101257324f;
        float ang = coords[b * Cc + c] * pf;
        v = fast_trig2(ang, which);   // which==0 -> sin, which==1 -> cos
    }
    __half h = __float2half_rn(v);
    g_pe_hi[idx] = h;
    g_pe_lo[idx] = __float2half_rn(v - __half2float(h));
}

// Transpose dec_W0 [K=102(->128), N=1024] -> g_w0t [n][k] fp16
__global__ void w0t_kernel(const float* __restrict__ W0)
{
    int idx = blockIdx.x * blockDim.x + threadIdx.x;
    if (idx >= Hh * INPAD2) return;
    int n = idx >> 7, k = idx & 127;
    float v = (k < INDIM) ? W0[(size_t)k * Hh + n] : 0.f;
    g_w0t[idx] = __float2half_rn(v);
}

// Transpose dec_Wh [4][K=1024][N=1024] -> g_wht [l][n][k] fp16
__global__ void wht_kernel(const float* __restrict__ Wh)
{
    size_t idx = (size_t)blockIdx.x * blockDim.x + threadIdx.x;
    if (idx >= 4 * (size_t)Hh * Hh) return;
    size_t l = idx >> 20;
    int n = (int)((idx >> 10) & 1023);
    int k = (int)(idx & 1023);
    g_wht[idx] = __float2half_rn(Wh[l * Hh * Hh + (size_t)k * Hh + n]);
}

// ---------------------------------------------------------------------------
// fp16 GEMM via mma.sync: C = relu(A@W + bias)
// Layer 0 (a_sel==0): A = Ah + Al (fp16 pair, 22-bit) -> 2 MMA terms.
// Hidden layers:      A = single fp16 -> 1 MMA term.
// Tile: CTA 128x128, BK=64, 4 warps (warp tile 64x64), 2-stage cp.async.
// B stored [n][k] K-major -> B fragments via PLAIN ldmatrix (non-trans).
// ---------------------------------------------------------------------------
__global__ __launch_bounds__(128, 2)
void gemm_mma_kernel(int a_sel, int w_sel, int bias_l, int out_sel, int K)
{
    extern __shared__ char dsm[];

    const bool twoterm = (a_sel == 0);
    const __half *Ahi, *Alo, *Bw;
    if (a_sel == 0)      { Ahi = g_pe_hi; Alo = g_pe_lo; }
    else if (a_sel == 1) { Ahi = g_h0; Alo = g_h0; }
    else                 { Ahi = g_h1; Alo = g_h1; }
    if (w_sel < 0) Bw = g_w0t;
    else           Bw = g_wht + (size_t)w_sel * Hh * Hh;
    __half* Oh = (out_sel == 0) ? g_h0 : g_h1;

    const int tid  = threadIdx.x;
    const int wid  = tid >> 5;
    const int lane = tid & 31;
    const int wm = wid >> 1;
    const int wn = wid & 1;
    const int n0 = blockIdx.x * BN;
    const size_t m0 = (size_t)blockIdx.y * BM;

    const uint32_t sbase = smem_u32(dsm);

    float acc[4][8][4];
    #pragma unroll
    for (int i = 0; i < 4; ++i)
        #pragma unroll
        for (int j = 0; j < 8; ++j)
            #pragma unroll
            for (int q = 0; q < 4; ++q) acc[i][j][q] = 0.f;

    const int nkt = K / BK;

    #define LOAD_STAGE(stg, kc) do {                                          \
        uint32_t bs = sbase + (stg) * STG_BYTES;                               \
        _Pragma("unroll")                                                      \
        for (int j = 0; j < 8; ++j) {                                          \
            int i = tid + j * 128;                                             \
            int row = i >> 3, u = i & 7;                                       \
            uint32_t dst = sw_addr(0, row, u);                                 \
            cp16(bs + OFF_AH + dst, Ahi + (m0 + row) * K + (kc) + u * 8);      \
            if (twoterm)                                                       \
                cp16(bs + OFF_AL + dst, Alo + (m0 + row) * K + (kc) + u * 8);  \
            cp16(bs + OFF_B  + dst, Bw + (size_t)(n0 + row) * K + (kc) + u * 8);\
        }                                                                      \
    } while (0)

    LOAD_STAGE(0, 0);
    CP_COMMIT();
    LOAD_STAGE(1, BK);
    CP_COMMIT();

    const int lr = lane & 15;
    const int lh = lane >> 4;

    for (int c = 0; c < nkt; ++c) {
        CP_WAIT1();
        __syncthreads();

        uint32_t sA = sbase + (c & 1) * STG_BYTES;

        #pragma unroll
        for (int ks = 0; ks < 4; ++ks) {
            uint32_t af[4][4], bb[4][4];
            int uu = ks * 2 + lh;
            #pragma unroll
            for (int mt = 0; mt < 4; ++mt)
                ldsm4(af[mt], sw_addr(sA + OFF_AH, wm * 64 + mt * 16 + lr, uu));
            #pragma unroll
            for (int g = 0; g < 4; ++g)
                ldsm4(bb[g], sw_addr(sA + OFF_B, wn * 64 + g * 16 + lr, uu));
            #pragma unroll
            for (int mt = 0; mt < 4; ++mt)
                #pragma unroll
                for (int nt = 0; nt < 8; ++nt)
                    mma16816(acc[mt][nt], af[mt],
                             bb[nt >> 1][nt & 1], bb[nt >> 1][2 + (nt & 1)]);
            if (twoterm) {
                #pragma unroll
                for (int mt = 0; mt < 4; ++mt)
                    ldsm4(af[mt], sw_addr(sA + OFF_AL, wm * 64 + mt * 16 + lr, uu));
                #pragma unroll
                for (int mt = 0; mt < 4; ++mt)
                    #pragma unroll
                    for (int nt = 0; nt < 8; ++nt)
                        mma16816(acc[mt][nt], af[mt],
                                 bb[nt >> 1][nt & 1], bb[nt >> 1][2 + (nt & 1)]);
            }
        }
        __syncthreads();
        if (c + 2 < nkt) LOAD_STAGE(c & 1, (c + 2) * BK);
        CP_COMMIT();
    }
    #undef LOAD_STAGE

    // ---- epilogue: bias + relu + fp16 stores ----
    const float* bias = g_bias + bias_l * Hh + n0 + wn * 64;
    const int qr = lane >> 2;
    const int qc = (lane & 3) * 2;

    #pragma unroll
    for (int mt = 0; mt < 4; ++mt) {
        size_t r0 = m0 + wm * 64 + mt * 16 + qr;
        size_t r1 = r0 + 8;
        #pragma unroll
        for (int nt = 0; nt < 8; ++nt) {
            int cl = nt * 8 + qc;
            int col = n0 + wn * 64 + cl;
            float b0 = bias[cl], b1 = bias[cl + 1];
            float v00 = fmaxf(acc[mt][nt][0] + b0, 0.f);
            float v01 = fmaxf(acc[mt][nt][1] + b1, 0.f);
            float v10 = fmaxf(acc[mt][nt][2] + b0, 0.f);
            float v11 = fmaxf(acc[mt][nt][3] + b1, 0.f);
            *(__half2*)(Oh + r0 * Hh + col) =
                __halves2half2(__float2half_rn(v00), __float2half_rn(v01));
            *(__half2*)(Oh + r1 * Hh + col) =
                __halves2half2(__float2half_rn(v10), __float2half_rn(v11));
        }
    }
}

// ---------------------------------------------------------------------------
// Output projection: values[B,3] = h @ Wout + bout. One warp/row.
// ---------------------------------------------------------------------------
__global__ void out_kernel(const float* __restrict__ Wout,
                           const float* __restrict__ bout,
                           float* __restrict__ out)
{
    int gwarp = (blockIdx.x * blockDim.x + threadIdx.x) >> 5;
    int lane = threadIdx.x & 31;
    if (gwarp >= Bn) return;
    const __half* hh = g_h0 + (size_t)gwarp * Hh;
    float a0 = 0.f, a1 = 0.f, a2 = 0.f;
    #pragma unroll 4
    for (int i = 0; i < 16; ++i) {
        int k = i * 64 + lane * 2;
        __half2 vh = *(const __half2*)(hh + k);
        float h0 = __half2float(__low2half(vh));
        float h1 = __half2float(__high2half(vh));
        a0 += h0 * Wout[k * 3 + 0] + h1 * Wout[(k + 1) * 3 + 0];
        a1 += h0 * Wout[k * 3 + 1] + h1 * Wout[(k + 1) * 3 + 1];
        a2 += h0 * Wout[k * 3 + 2] + h1 * Wout[(k + 1) * 3 + 2];
    }
    #pragma unroll
    for (int off = 16; off; off >>= 1) {
        a0 += __shfl_down_sync(0xffffffffu, a0, off);
        a1 += __shfl_down_sync(0xffffffffu, a1, off);
        a2 += __shfl_down_sync(0xffffffffu, a2, off);
    }
    if (lane == 0) {
        out[gwarp * 3 + 0] = a0 + bout[0];
        out[gwarp * 3 + 1] = a1 + bout[1];
        out[gwarp * 3 + 2] = a2 + bout[2];
    }
}

// ---------------------------------------------------------------------------
extern "C" void kernel_launch(void* const* d_in, const int* in_sizes, int n_in,
                              void* d_out, int out_size)
{
    const float* coords     = (const float*)d_in[0];
    const int*   latent_idx = (const int*)  d_in[1];
    const float* latents    = (const float*)d_in[2];
    const float* codebooks  = (const float*)d_in[3];
    const float* mod_W      = (const float*)d_in[4];
    const float* mod_b      = (const float*)d_in[5];
    const float* dec_W0     = (const float*)d_in[6];
    const float* dec_b0     = (const float*)d_in[7];
    const float* dec_Wh     = (const float*)d_in[8];
    const float* dec_bh     = (const float*)d_in[9];
    const float* dec_Wout   = (const float*)d_in[10];
    const float* dec_bout   = (const float*)d_in[11];
    float* out = (float*)d_out;

    cudaFuncSetAttribute(gemm_mma_kernel,
                         cudaFuncAttributeMaxDynamicSharedMemorySize, SMEM_DYN);

    setup_kernel<<<1, 1024>>>(latent_idx, latents, codebooks, out, out_size);
    bias_kernel<<<(Ll * Hh + 127) / 128, 128>>>(mod_W, mod_b, dec_b0, dec_bh);
    pe_kernel<<<(Bn * INPAD2 + 255) / 256, 256>>>(coords);
    w0t_kernel<<<(Hh * INPAD2 + 255) / 256, 256>>>(dec_W0);
    wht_kernel<<<(int)((4 * (size_t)Hh * Hh + 255) / 256), 256>>>(dec_Wh);

    dim3 grid(Hh / BN, Bn / BM);   // (8, 512)
    // L0: pe @ W0t -> h0 (2-term: pe hi+lo)
    gemm_mma_kernel<<<grid, 128, SMEM_DYN>>>(0, -1, 0, 0, INPAD2);
    // hidden layers ping-pong h0 <-> h1 (1-term fp16)
    gemm_mma_kernel<<<grid, 128, SMEM_DYN>>>(1, 0, 1, 1, Hh);
    gemm_mma_kernel<<<grid, 128, SMEM_DYN>>>(2, 1, 2, 0, Hh);
    gemm_mma_kernel<<<grid, 128, SMEM_DYN>>>(1, 2, 3, 1, Hh);
    gemm_mma_kernel<<<grid, 128, SMEM_DYN>>>(2, 3, 4, 0, Hh);
    // output projection reads h0
    out_kernel<<<(Bn * 32 + 255) / 256, 256>>>(dec_Wout, dec_bout, out);
}